// round 1
// baseline (speedup 1.0000x reference)
#include <cuda_runtime.h>

// Problem constants (fixed by the dataset)
#define NN   100000
#define EE   1600000
#define HH   64
#define FIN  14
#define GG   512

// ---------------- scratch (device globals; no allocation allowed) ----------
__device__ __align__(16) float g_deg[NN];
__device__ __align__(16) float g_dis[NN];        // deg^{-1/2}
__device__ __align__(16) float g_dinv[NN];       // 1/deg  (self-loop weight)
__device__ __align__(16) float g_norm[EE];       // per-edge weight
__device__ __align__(16) float g_aggx[NN * FIN]; // layer-1 aggregated features
__device__ __align__(16) float g_m[NN * HH];     // per-layer m = h @ W
__device__ __align__(16) float g_buf0[NN * HH];  // ping
__device__ __align__(16) float g_buf1[NN * HH];  // pong
__device__ __align__(16) float g_pool[GG * HH];  // max-pooled

// ---------------- small prep kernels ---------------------------------------
__global__ void k_zero() {
    int i = blockIdx.x * blockDim.x + threadIdx.x;
    if (i < NN) g_deg[i] = 0.0f;
    if (i < GG * HH) g_pool[i] = 0.0f;  // bits 0 == 0.0f; relu outputs are >= 0
}

__global__ void k_deg(const int* __restrict__ dst) {
    int e = blockIdx.x * blockDim.x + threadIdx.x;
    if (e < EE) atomicAdd(&g_deg[dst[e]], 1.0f);
}

__global__ void k_prep() {
    int i = blockIdx.x * blockDim.x + threadIdx.x;
    if (i < NN) {
        float d  = g_deg[i] + 1.0f;
        float ds = rsqrtf(d);
        g_dis[i]  = ds;
        g_dinv[i] = 1.0f / d;
    }
}

__global__ void k_norm(const int* __restrict__ src, const int* __restrict__ dst) {
    int e = blockIdx.x * blockDim.x + threadIdx.x;
    if (e < EE) g_norm[e] = g_dis[src[e]] * g_dis[dst[e]];
}

// ---------------- layer 1: aggregate x (14-wide) BEFORE the GEMM -----------
__global__ void k_self14(const float* __restrict__ x) {
    int i = blockIdx.x * blockDim.x + threadIdx.x;
    if (i < NN) {
        float dv = g_dinv[i];
        #pragma unroll
        for (int j = 0; j < FIN; j++)
            g_aggx[i * FIN + j] = x[i * FIN + j] * dv;
    }
}

// one edge handled by 7 threads, 2 floats each (14 = 7*2, 8B aligned rows)
__global__ void k_scat14(const int* __restrict__ src, const int* __restrict__ dst,
                         const float* __restrict__ x) {
    int idx = blockIdx.x * blockDim.x + threadIdx.x;  // < EE*7
    if (idx >= EE * 7) return;
    int e = idx / 7, c = idx - e * 7;
    float nrm = g_norm[e];
    int s = src[e], d = dst[e];
    float2 v = *(const float2*)(x + s * FIN + c * 2);
    float* p = g_aggx + d * FIN + c * 2;
    asm volatile("red.global.add.v2.f32 [%0], {%1,%2};"
                 :: "l"(p), "f"(v.x * nrm), "f"(v.y * nrm) : "memory");
}

// h1_pre = aggx @ W1 + b1   (no relu stored; relu applied on read downstream)
__global__ void k_gemm1(const float* __restrict__ W1, const float* __restrict__ b1) {
    int idx = blockIdx.x * blockDim.x + threadIdx.x;  // < NN*HH
    if (idx >= NN * HH) return;
    int i = idx >> 6, j = idx & 63;
    float acc = b1[j];
    #pragma unroll
    for (int k = 0; k < FIN; k++)
        acc += g_aggx[i * FIN + k] * W1[k * HH + j];
    g_buf0[idx] = acc;
}

// ---------------- layers 2..5: fused GEMM + self-loop init -----------------
// in = relu(buf[cur]); m = in @ W; agg_out = m*dinv + b  (scatter adds later)
__global__ void __launch_bounds__(256)
k_gemm64(const float* __restrict__ W, const float* __restrict__ b,
         int cur) {
    const float* in   = cur ? g_buf1 : g_buf0;
    float* agg_out    = cur ? g_buf0 : g_buf1;

    __shared__ float ws[64 * 64];   // W[k][j]
    __shared__ float hs[64 * 68];   // transposed: hs[k*68 + r], padded stride

    int tid  = threadIdx.x;
    int row0 = blockIdx.x * 64;

    #pragma unroll
    for (int t = 0; t < 16; t++)
        ws[t * 256 + tid] = W[t * 256 + tid];

    #pragma unroll
    for (int t = 0; t < 16; t++) {
        int idx = t * 256 + tid;
        int r = idx >> 6, k = idx & 63;
        int row = row0 + r;
        float v = (row < NN) ? in[row * 64 + k] : 0.0f;
        hs[k * 68 + r] = fmaxf(v, 0.0f);           // fused relu
    }
    __syncthreads();

    int tx = tid & 15, ty = tid >> 4;              // 16x16 threads, 4x4 tile
    float acc[4][4];
    #pragma unroll
    for (int i = 0; i < 4; i++)
        #pragma unroll
        for (int j = 0; j < 4; j++) acc[i][j] = 0.0f;

    #pragma unroll 8
    for (int k = 0; k < 64; k++) {
        float4 a  = *(const float4*)&hs[k * 68 + ty * 4];
        float4 w4 = *(const float4*)&ws[k * 64 + tx * 4];
        float av[4] = {a.x, a.y, a.z, a.w};
        float wv[4] = {w4.x, w4.y, w4.z, w4.w};
        #pragma unroll
        for (int i = 0; i < 4; i++)
            #pragma unroll
            for (int j = 0; j < 4; j++)
                acc[i][j] += av[i] * wv[j];
    }

    float4 bj = *(const float4*)&b[tx * 4];
    float bv[4] = {bj.x, bj.y, bj.z, bj.w};
    #pragma unroll
    for (int i = 0; i < 4; i++) {
        int row = row0 + ty * 4 + i;
        if (row < NN) {
            float dv = g_dinv[row];
            float4 mv = make_float4(acc[i][0], acc[i][1], acc[i][2], acc[i][3]);
            *(float4*)&g_m[row * 64 + tx * 4] = mv;
            float4 av = make_float4(acc[i][0] * dv + bv[0],
                                    acc[i][1] * dv + bv[1],
                                    acc[i][2] * dv + bv[2],
                                    acc[i][3] * dv + bv[3]);
            *(float4*)&agg_out[row * 64 + tx * 4] = av;
        }
    }
}

// one edge handled by 16 threads, float4 each (64 floats)
__global__ void k_scat64(const int* __restrict__ src, const int* __restrict__ dst,
                         int cur) {
    float* agg = cur ? g_buf0 : g_buf1;   // same buffer k_gemm64 wrote with cur
    int idx = blockIdx.x * blockDim.x + threadIdx.x;  // < EE*16
    if (idx >= EE * 16) return;
    int e = idx >> 4, c = idx & 15;
    float nrm = g_norm[e];
    int s = src[e], d = dst[e];
    float4 v = *(const float4*)&g_m[s * 64 + c * 4];
    float* p = agg + d * 64 + c * 4;
    asm volatile("red.global.add.v4.f32 [%0], {%1,%2,%3,%4};"
                 :: "l"(p), "f"(v.x * nrm), "f"(v.y * nrm),
                    "f"(v.z * nrm), "f"(v.w * nrm) : "memory");
}

// ---------------- pooling + head --------------------------------------------
__global__ void k_pool(const int* __restrict__ batch, int cur) {
    const float* hin = cur ? g_buf1 : g_buf0;
    int idx = blockIdx.x * blockDim.x + threadIdx.x;  // < NN*64
    if (idx >= NN * 64) return;
    int i = idx >> 6, j = idx & 63;
    float v = fmaxf(hin[idx], 0.0f);                  // fused relu
    atomicMax((unsigned int*)&g_pool[batch[i] * 64 + j], __float_as_uint(v));
}

__global__ void k_final(const float* __restrict__ Wl, const float* __restrict__ bl,
                        float* __restrict__ out) {
    int g = blockIdx.x * blockDim.x + threadIdx.x;
    if (g >= GG) return;
    float a0 = bl[0], a1 = bl[1];
    #pragma unroll
    for (int k = 0; k < HH; k++) {
        float p = g_pool[g * HH + k];
        a0 += p * Wl[k * 2 + 0];
        a1 += p * Wl[k * 2 + 1];
    }
    out[g * 2 + 0] = a0;
    out[g * 2 + 1] = a1;
}

// ---------------- launch -----------------------------------------------------
extern "C" void kernel_launch(void* const* d_in, const int* in_sizes, int n_in,
                              void* d_out, int out_size) {
    const float* x    = (const float*)d_in[0];
    const float* W1   = (const float*)d_in[1];
    const float* b1   = (const float*)d_in[2];
    const int*   ei   = (const int*)d_in[13];
    const int*   batc = (const int*)d_in[14];
    const int* src = ei;
    const int* dst = ei + EE;
    float* out = (float*)d_out;

    const int T = 256;
    k_zero  <<<(NN + T - 1) / T, T>>>();
    k_deg   <<<(EE + T - 1) / T, T>>>(dst);
    k_prep  <<<(NN + T - 1) / T, T>>>();
    k_norm  <<<(EE + T - 1) / T, T>>>(src, dst);

    // layer 1: aggregate x (14-wide) then GEMM
    k_self14<<<(NN + T - 1) / T, T>>>(x);
    k_scat14<<<(EE * 7 + T - 1) / T, T>>>(src, dst, x);
    k_gemm1 <<<(NN * HH + T - 1) / T, T>>>(W1, b1);

    // layers 2..5
    int cur = 0;
    for (int l = 0; l < 4; l++) {
        const float* W = (const float*)d_in[3 + 2 * l];
        const float* b = (const float*)d_in[4 + 2 * l];
        k_gemm64<<<(NN + 63) / 64, 256>>>(W, b, cur);
        k_scat64<<<(EE * 16 + T - 1) / T, T>>>(src, dst, cur);
        cur ^= 1;
    }

    k_pool <<<(NN * HH + T - 1) / T, T>>>(batc, cur);
    k_final<<<(GG + T - 1) / T, T>>>((const float*)d_in[11], (const float*)d_in[12], out);
}

// round 2
// speedup vs baseline: 1.5380x; 1.5380x over previous
#include <cuda_runtime.h>

#define NN   100000
#define EE   1600000
#define HH   64
#define FIN  14
#define GG   512
#define NBLK 391           // ceil(NN/256)

// ---------------- scratch (device globals) ----------------------------------
__device__ int   g_degc[NN];
__device__ int   g_off[NN + 1];      // CSR offsets by dst
__device__ int   g_cur[NN];          // fill cursors
__device__ int   g_bsum[512];
__device__ int   g_boff[512];
__device__ float g_dis[NN];          // deg^{-1/2}
__device__ float g_dinv[NN];         // 1/deg
__device__ __align__(16) int2  g_epack[EE];      // (src, norm bits) sorted by dst
__device__ __align__(16) float g_aggx[NN * FIN];
__device__ __align__(16) float g_m[NN * HH];
__device__ __align__(16) float g_h[NN * HH];
__device__ int   g_gstart[GG + 1];

// ---------------- prep -------------------------------------------------------
__global__ void k_init() {
    int i = blockIdx.x * blockDim.x + threadIdx.x;
    if (i < NN) g_degc[i] = 0;
}

__global__ void k_deg(const int* __restrict__ dst) {
    int e = blockIdx.x * blockDim.x + threadIdx.x;
    if (e < EE) atomicAdd(&g_degc[dst[e]], 1);
}

__global__ void k_scanA() {
    __shared__ int s[256];
    int i = blockIdx.x * 256 + threadIdx.x;
    int v = (i < NN) ? g_degc[i] : 0;
    s[threadIdx.x] = v;
    __syncthreads();
    #pragma unroll
    for (int o = 1; o < 256; o <<= 1) {
        int t = (threadIdx.x >= o) ? s[threadIdx.x - o] : 0;
        __syncthreads();
        s[threadIdx.x] += t;
        __syncthreads();
    }
    if (i < NN) g_off[i] = s[threadIdx.x] - v;    // exclusive
    if (threadIdx.x == 255) g_bsum[blockIdx.x] = s[255];
}

__global__ void k_scanB() {
    __shared__ int s[512];
    int t = threadIdx.x;
    int v = (t < NBLK) ? g_bsum[t] : 0;
    s[t] = v;
    __syncthreads();
    #pragma unroll
    for (int o = 1; o < 512; o <<= 1) {
        int u = (t >= o) ? s[t - o] : 0;
        __syncthreads();
        s[t] += u;
        __syncthreads();
    }
    if (t < NBLK) g_boff[t] = s[t] - v;           // exclusive
}

__global__ void k_scanC() {
    int i = blockIdx.x * blockDim.x + threadIdx.x;
    if (i >= NN) return;
    int o = g_off[i] + g_boff[i >> 8];
    g_off[i] = o;
    g_cur[i] = o;
    float d = (float)(g_degc[i] + 1);
    g_dis[i]  = rsqrtf(d);
    g_dinv[i] = 1.0f / d;
    if (i == 0) g_off[NN] = EE;
}

__global__ void k_fill(const int* __restrict__ src, const int* __restrict__ dst) {
    int e = blockIdx.x * blockDim.x + threadIdx.x;
    if (e >= EE) return;
    int s = src[e], d = dst[e];
    float nrm = g_dis[s] * g_dis[d];
    int p = atomicAdd(&g_cur[d], 1);
    g_epack[p] = make_int2(s, __float_as_int(nrm));
}

__global__ void k_gb(const int* __restrict__ batch) {
    int i = blockIdx.x * blockDim.x + threadIdx.x;
    if (i >= NN) return;
    int b = batch[i];
    int pb = (i == 0) ? -1 : batch[i - 1];
    for (int g = pb + 1; g <= b; g++) g_gstart[g] = i;
    if (i == NN - 1)
        for (int g = b + 1; g <= GG; g++) g_gstart[g] = NN;
}

// ---------------- layer 1: gather-aggregate x (14-wide) then GEMM ----------
__global__ void k_agg14(const float* __restrict__ x) {
    int gidx = blockIdx.x * blockDim.x + threadIdx.x;  // NN*8
    int node = gidx >> 3, c = gidx & 7;
    if (node >= NN) return;
    int beg = g_off[node], end = g_off[node + 1];
    bool act = (c < 7);
    float ax = 0.0f, ay = 0.0f;
    for (int j = beg; j < end; j++) {
        int2 p = g_epack[j];
        float nrm = __int_as_float(p.y);
        if (act) {
            float2 xv = *(const float2*)&x[p.x * FIN + c * 2];
            ax += nrm * xv.x;
            ay += nrm * xv.y;
        }
    }
    if (act) {
        float dv = g_dinv[node];
        float2 xs = *(const float2*)&x[node * FIN + c * 2];
        ax += dv * xs.x;
        ay += dv * xs.y;
        *(float2*)&g_aggx[node * FIN + c * 2] = make_float2(ax, ay);
    }
}

__global__ void k_gemm1(const float* __restrict__ W1, const float* __restrict__ b1) {
    int idx = blockIdx.x * blockDim.x + threadIdx.x;
    if (idx >= NN * HH) return;
    int i = idx >> 6, j = idx & 63;
    float acc = b1[j];
    #pragma unroll
    for (int k = 0; k < FIN; k++)
        acc += g_aggx[i * FIN + k] * W1[k * HH + j];
    g_h[idx] = fmaxf(acc, 0.0f);   // relu applied; h holds relu'ed activations
}

// ---------------- layers 2..5 ------------------------------------------------
// m = h @ W   (h already relu'ed)
__global__ void __launch_bounds__(128)
k_gemm64(const float* __restrict__ W) {
    __shared__ float ws[64 * 64];
    __shared__ float hs[64 * 68];    // transposed [k][r], padded
    int tid = threadIdx.x;
    int row0 = blockIdx.x * 64;

    #pragma unroll
    for (int t = 0; t < 32; t++)
        ws[t * 128 + tid] = W[t * 128 + tid];

    #pragma unroll
    for (int t = 0; t < 32; t++) {
        int idx = t * 128 + tid;
        int r = idx >> 6, k = idx & 63;
        int row = row0 + r;
        hs[k * 68 + r] = (row < NN) ? g_h[row * 64 + k] : 0.0f;
    }
    __syncthreads();

    int tx = tid & 7, ty = tid >> 3;          // 8x16 threads, 4 rows x 8 cols each
    float acc[4][8];
    #pragma unroll
    for (int i = 0; i < 4; i++)
        #pragma unroll
        for (int j = 0; j < 8; j++) acc[i][j] = 0.0f;

    #pragma unroll 8
    for (int k = 0; k < 64; k++) {
        float4 a  = *(const float4*)&hs[k * 68 + ty * 4];
        float4 w0 = *(const float4*)&ws[k * 64 + tx * 8];
        float4 w1 = *(const float4*)&ws[k * 64 + tx * 8 + 4];
        float av[4] = {a.x, a.y, a.z, a.w};
        float wv[8] = {w0.x, w0.y, w0.z, w0.w, w1.x, w1.y, w1.z, w1.w};
        #pragma unroll
        for (int i = 0; i < 4; i++)
            #pragma unroll
            for (int j = 0; j < 8; j++)
                acc[i][j] += av[i] * wv[j];
    }

    #pragma unroll
    for (int i = 0; i < 4; i++) {
        int row = row0 + ty * 4 + i;
        if (row < NN) {
            *(float4*)&g_m[row * 64 + tx * 8]     = make_float4(acc[i][0], acc[i][1], acc[i][2], acc[i][3]);
            *(float4*)&g_m[row * 64 + tx * 8 + 4] = make_float4(acc[i][4], acc[i][5], acc[i][6], acc[i][7]);
        }
    }
}

// h = relu( gather(norm * m[src]) + m*dinv + b )   — 16 lanes per node
__global__ void __launch_bounds__(256)
k_agg64(const float* __restrict__ b) {
    int t = threadIdx.x;
    int node = blockIdx.x * 16 + (t >> 4);
    int c = t & 15;
    if (node >= NN) return;
    int beg = g_off[node], end = g_off[node + 1];

    float4 acc = make_float4(0.f, 0.f, 0.f, 0.f);
    int j = beg;
    for (; j + 1 < end; j += 2) {
        int2 p0 = g_epack[j];
        int2 p1 = g_epack[j + 1];
        float n0 = __int_as_float(p0.y);
        float n1 = __int_as_float(p1.y);
        float4 v0 = *(const float4*)&g_m[p0.x * 64 + c * 4];
        float4 v1 = *(const float4*)&g_m[p1.x * 64 + c * 4];
        acc.x += n0 * v0.x + n1 * v1.x;
        acc.y += n0 * v0.y + n1 * v1.y;
        acc.z += n0 * v0.z + n1 * v1.z;
        acc.w += n0 * v0.w + n1 * v1.w;
    }
    if (j < end) {
        int2 p = g_epack[j];
        float n = __int_as_float(p.y);
        float4 v = *(const float4*)&g_m[p.x * 64 + c * 4];
        acc.x += n * v.x; acc.y += n * v.y; acc.z += n * v.z; acc.w += n * v.w;
    }

    float dv = g_dinv[node];
    float4 mv = *(const float4*)&g_m[node * 64 + c * 4];
    float4 bb = *(const float4*)&b[c * 4];
    float4 o;
    o.x = fmaxf(acc.x + dv * mv.x + bb.x, 0.0f);
    o.y = fmaxf(acc.y + dv * mv.y + bb.y, 0.0f);
    o.z = fmaxf(acc.z + dv * mv.z + bb.z, 0.0f);
    o.w = fmaxf(acc.w + dv * mv.w + bb.w, 0.0f);
    *(float4*)&g_h[node * 64 + c * 4] = o;
}

// ---------------- pooling + head (fused), one block per graph ---------------
__global__ void __launch_bounds__(256)
k_pool(const float* __restrict__ Wl, const float* __restrict__ bl,
       float* __restrict__ out) {
    int g = blockIdx.x;
    int s = g_gstart[g], e = g_gstart[g + 1];
    int tid = threadIdx.x;
    int j = tid & 63, r = tid >> 6;

    float mx = 0.0f;    // relu'ed values >= 0; nonempty graphs -> max >= 0
    for (int i = s + r; i < e; i += 4)
        mx = fmaxf(mx, g_h[i * 64 + j]);

    __shared__ float sm[256];
    sm[tid] = mx;
    __syncthreads();
    if (tid < 64) {
        float p = fmaxf(fmaxf(sm[tid], sm[tid + 64]),
                        fmaxf(sm[tid + 128], sm[tid + 192]));
        sm[tid]      = p * Wl[tid * 2];
        sm[tid + 64] = p * Wl[tid * 2 + 1];
    }
    __syncthreads();
    #pragma unroll
    for (int o = 32; o >= 1; o >>= 1) {
        if (tid < o) {
            sm[tid]      += sm[tid + o];
            sm[tid + 64] += sm[tid + 64 + o];
        }
        __syncthreads();
    }
    if (tid == 0) {
        out[g * 2]     = sm[0]  + bl[0];
        out[g * 2 + 1] = sm[64] + bl[1];
    }
}

// ---------------- launch -----------------------------------------------------
extern "C" void kernel_launch(void* const* d_in, const int* in_sizes, int n_in,
                              void* d_out, int out_size) {
    const float* x  = (const float*)d_in[0];
    const int*   ei = (const int*)d_in[13];
    const int*   bt = (const int*)d_in[14];
    const int* src = ei;
    const int* dst = ei + EE;
    float* out = (float*)d_out;

    const int T = 256;
    k_init <<<NBLK, T>>>();
    k_deg  <<<(EE + T - 1) / T, T>>>(dst);
    k_scanA<<<NBLK, T>>>();
    k_scanB<<<1, 512>>>();
    k_scanC<<<NBLK, T>>>();
    k_fill <<<(EE + T - 1) / T, T>>>(src, dst);
    k_gb   <<<NBLK, T>>>(bt);

    // layer 1
    k_agg14<<<(NN * 8 + T - 1) / T, T>>>(x);
    k_gemm1<<<(NN * HH + T - 1) / T, T>>>((const float*)d_in[1], (const float*)d_in[2]);

    // layers 2..5
    for (int l = 0; l < 4; l++) {
        const float* W = (const float*)d_in[3 + 2 * l];
        const float* b = (const float*)d_in[4 + 2 * l];
        k_gemm64<<<(NN + 63) / 64, 128>>>(W);
        k_agg64 <<<(NN + 15) / 16, 256>>>(b);
    }

    k_pool<<<GG, 256>>>((const float*)d_in[11], (const float*)d_in[12], out);
}